// round 12
// baseline (speedup 1.0000x reference)
#include <cuda_runtime.h>

// Problem constants
#define BC        20      // B*C
#define HLEN      200     // his_length
#define DK        20
#define NROWS     4000    // BC*HLEN
#define ROW_ELEMS 8000    // D_INNER(400) * DK(20)
#define CTX_ELEMS (NROWS*DK)        // 80000
#define ATTN_OFF  CTX_ELEMS

// Projected q,k,v,c in TRANSPOSED layout: [bc][d][h] -> (bc*20+d)*200+h
__device__ float g_qT[CTX_ELEMS];
__device__ float g_kT[CTX_ELEMS];
__device__ float g_vT[CTX_ELEMS];
__device__ float g_cT[CTX_ELEMS];

// ---------------------------------------------------------------------------
// Kernel 1: projections.  grid = (row 0..3999, tensor 0..2); 200 threads.
// (82.8% DRAM in R5 — near streaming roofline; unchanged.)
// ---------------------------------------------------------------------------
__global__ __launch_bounds__(200) void proj_kernel(
    const float* __restrict__ Q, const float* __restrict__ K,
    const float* __restrict__ V, const float* __restrict__ cdd,
    const float* __restrict__ W, const float* __restrict__ bp,
    const float* __restrict__ W1, const float* __restrict__ b1p)
{
    __shared__ float Ws[400];
    __shared__ float4 red[200];

    const int r = blockIdx.x;      // row 0..3999
    const int a = blockIdx.y;      // tensor 0..2
    const int t = threadIdx.x;     // 0..199
    const int bc = r / HLEN;
    const int h  = r - bc * HLEN;

    Ws[t]       = W[t];
    Ws[t + 200] = W[t + 200];
    __syncthreads();

    const float bias = __ldg(bp);
    const size_t base = (size_t)r * ROW_ELEMS;

    const float* src = (a == 0) ? (Q + base) : (a == 1) ? (K + base) : (V + base);
    float*       dst = (a == 0) ? g_qT : (a == 1) ? g_kT : g_vT;

    const float4* p = (const float4*)src;
    float acc0 = 0.f, acc1 = 0.f, acc2 = 0.f, acc3 = 0.f;
    #pragma unroll
    for (int j = 0; j < 10; j++) {
        const int i4 = t + 200 * j;
        const float4 v4 = p[i4];
        const float w = Ws[(i4 * 4) / 20];     // same n for all 4 lanes
        acc0 += v4.x * w;
        acc1 += v4.y * w;
        acc2 += v4.z * w;
        acc3 += v4.w * w;
    }
    red[t] = make_float4(acc0, acc1, acc2, acc3);
    __syncthreads();

    if (t < 20) {
        const int e  = t & 3;
        const int st = t >> 2;
        float s = bias;
        #pragma unroll 8
        for (int tp = st; tp < 200; tp += 5)
            s += ((const float*)&red[tp])[e];
        dst[(bc * DK + t) * HLEN + h] = s;
    }

    if (a == 2 && t < 20) {
        const float b1 = __ldg(b1p);
        const float* cb = cdd + (size_t)r * 400;
        float s = b1;
        #pragma unroll
        for (int n = 0; n < 20; n++)
            s += cb[n * 20 + t] * __ldg(W1 + n);
        g_cT[(bc * DK + t) * HLEN + h] = s;
    }
}

// ---------------------------------------------------------------------------
// Kernel 2 (fused attention, v3).  grid = (bc=20, mt=20); 160 threads
// (5 warps).  Warp w owns TWO rows ma=m0+2w, mb=ma+1 (m-register-tiling:
// every ys/vt shared load feeds 2 FMAs).  Lane covers n = lane + 32*j, j<7
// (stride-1, conflict-free).  ys/vt padded to 224 cols (zeros) -> no guards
// in the score loop.  Softmax denominator and the 20 context dims are
// warp-local (shfl butterflies) — no cross-warp partials, one syncthreads.
// smem (floats): ys 40*224=8960, vt 20*224=4480, xs 400 -> 13840 (55.4KB)
// ---------------------------------------------------------------------------
#define YSTR  224
#define Y4    56                  // YSTR/4
#define SMEM_FLOATS (40*YSTR + 20*YSTR + 400)
#define SMEM_BYTES  (SMEM_FLOATS * 4)

__global__ __launch_bounds__(160, 4) void attn_fused(float* __restrict__ out)
{
    extern __shared__ float sm[];
    float* ys = sm;                 // [d][n] d<40, padded
    float* vt = sm + 40 * YSTR;     // [d][n] d<20, padded
    float* xs = sm + 60 * YSTR;     // [d][m] d<40, m<10

    const int bc = blockIdx.x;
    const int m0 = blockIdx.y * 10;
    const int t  = threadIdx.x;
    const int w    = t >> 5;
    const int lane = t & 31;

    // ---- stage (float4 LDG from transposed gmem, zero-pad cols 200..223) --
    float4* ys4 = (float4*)ys;
    for (int i = t; i < 40 * Y4; i += 160) {
        const int d = i / Y4, n4 = i - Y4 * d;
        float4 v = make_float4(0.f, 0.f, 0.f, 0.f);
        if (n4 < 50)
            v = (d < 20) ? ((const float4*)(g_kT + (bc * DK + d) * HLEN))[n4]
                         : ((const float4*)(g_cT + (bc * DK + d - 20) * HLEN))[n4];
        ys4[i] = v;
    }
    float4* vt4 = (float4*)vt;
    for (int i = t; i < 20 * Y4; i += 160) {
        const int d = i / Y4, n4 = i - Y4 * d;
        float4 v = make_float4(0.f, 0.f, 0.f, 0.f);
        if (n4 < 50)
            v = ((const float4*)(g_vT + (bc * DK + d) * HLEN))[n4];
        vt4[i] = v;
    }
    for (int i = t; i < 400; i += 160) {
        const int d = i / 10, m = i - 10 * d;
        xs[i] = (d < 20) ? g_qT[(bc * DK + d) * HLEN + m0 + m]
                         : g_kT[(bc * DK + d - 20) * HLEN + m0 + m];
    }
    __syncthreads();

    const int la = 2 * w, lb = la + 1;       // local rows
    const int ma = m0 + la, mb = m0 + lb;

    // ---- scores: 2 rows per warp, 7 n per lane ----
    float s0[7], s1[7];
    #pragma unroll
    for (int j = 0; j < 7; j++) { s0[j] = 0.f; s1[j] = 0.f; }

    #pragma unroll 8
    for (int d = 0; d < 40; d++) {
        const float xa = xs[d * 10 + la];    // broadcast
        const float xb = xs[d * 10 + lb];    // broadcast
        #pragma unroll
        for (int j = 0; j < 7; j++) {
            const float y = ys[d * YSTR + lane + 32 * j];
            s0[j] += xa * y;
            s1[j] += xb * y;
        }
    }

    const float isd = 0.22360679774997896f;  // 1/sqrt(20)
    float e0[7], e1[7];
    float sum0 = 0.f, sum1 = 0.f;
    #pragma unroll
    for (int j = 0; j < 7; j++) {
        const bool valid = (lane + 32 * j) < HLEN;
        e0[j] = valid ? __expf(s0[j] * isd) : 0.f;
        e1[j] = valid ? __expf(s1[j] * isd) : 0.f;
        sum0 += e0[j];
        sum1 += e1[j];
    }
    #pragma unroll
    for (int o = 16; o; o >>= 1) {
        sum0 += __shfl_xor_sync(0xFFFFFFFFu, sum0, o);
        sum1 += __shfl_xor_sync(0xFFFFFFFFu, sum1, o);
    }
    const float rs0 = 1.f / (sum0 + 1e-8f);
    const float rs1 = 1.f / (sum1 + 1e-8f);

    // ---- normalized attn writes (coalesced) ----
    float* attnA = out + ATTN_OFF + (size_t)(bc * HLEN + ma) * HLEN;
    float* attnB = out + ATTN_OFF + (size_t)(bc * HLEN + mb) * HLEN;
    #pragma unroll
    for (int j = 0; j < 7; j++) {
        const int n = lane + 32 * j;
        if (n < HLEN) {
            attnA[n] = e0[j] * rs0;
            attnB[n] = e1[j] * rs1;
        }
    }

    // ---- context: unnormalized accumulate, each vt load feeds 2 rows ----
    float c0[DK], c1[DK];
    #pragma unroll
    for (int d = 0; d < DK; d++) { c0[d] = 0.f; c1[d] = 0.f; }

    #pragma unroll 4
    for (int d = 0; d < DK; d++) {
        #pragma unroll
        for (int j = 0; j < 7; j++) {
            const float v = vt[d * YSTR + lane + 32 * j];
            c0[d] += e0[j] * v;
            c1[d] += e1[j] * v;
        }
    }

    // ---- warp-local context reduce ----
    #pragma unroll
    for (int d = 0; d < DK; d++) {
        #pragma unroll
        for (int o = 16; o; o >>= 1) {
            c0[d] += __shfl_xor_sync(0xFFFFFFFFu, c0[d], o);
            c1[d] += __shfl_xor_sync(0xFFFFFFFFu, c1[d], o);
        }
    }

    // lane d extracts dim d (compile-time unrolled predicated moves)
    float o0 = 0.f, o1 = 0.f;
    #pragma unroll
    for (int d = 0; d < DK; d++)
        if (lane == d) { o0 = c0[d]; o1 = c1[d]; }
    if (lane < DK) {
        out[(bc * HLEN + ma) * DK + lane] = o0 * rs0;
        out[(bc * HLEN + mb) * DK + lane] = o1 * rs1;
    }
}

extern "C" void kernel_launch(void* const* d_in, const int* in_sizes, int n_in,
                              void* d_out, int out_size)
{
    const float* Q   = (const float*)d_in[0];
    const float* K   = (const float*)d_in[1];
    const float* V   = (const float*)d_in[2];
    const float* cdd = (const float*)d_in[3];
    const float* W   = (const float*)d_in[4];
    const float* b   = (const float*)d_in[5];
    const float* W1  = (const float*)d_in[6];
    const float* b1  = (const float*)d_in[7];

    cudaFuncSetAttribute(attn_fused,
                         cudaFuncAttributeMaxDynamicSharedMemorySize, SMEM_BYTES);

    proj_kernel<<<dim3(NROWS, 3), 200>>>(Q, K, V, cdd, W, b, W1, b1);
    attn_fused<<<dim3(BC, 20), 160, SMEM_BYTES>>>((float*)d_out);
}